// round 10
// baseline (speedup 1.0000x reference)
#include <cuda_runtime.h>
#include <cuda_bf16.h>

#define SIDE 9
#define STATE 81
#define NA 5
#define H 32
#define WARPS_K1 8
#define MAX_B 131072

// nsc transposed scratch: [d][b]
__device__ float g_nscT[(size_t)STATE * MAX_B];

// ---------------------------------------------------------------------------
// K1: warp-per-row scatter + reward + transposed scratch write (round-7 form).
// ---------------------------------------------------------------------------
__global__ __launch_bounds__(32 * WARPS_K1) void k1_nsc_reward(
    const float* __restrict__ obs,          // (B, 3*STATE)
    const float* __restrict__ acr_g,        // (B, STATE*NA)
    float* __restrict__ out,                // [sym(B), imm(B), ret(B), nsc(B*81)]
    int B)
{
    __shared__ float s_ac[WARPS_K1][416];
    __shared__ float s_nsc[WARPS_K1 * STATE];

    const int tid  = threadIdx.x;
    const int wid  = tid >> 5;
    const int lane = tid & 31;
    const long long row0 = (long long)blockIdx.x * WARPS_K1;
    const long long row  = row0 + wid;

    if (row < B) {
        const float* __restrict__ acr = acr_g + row * (STATE * NA);
        float* __restrict__ sp = s_ac[wid];
        #pragma unroll
        for (int k = 0; k < 13; k++) {
            const int i = lane + 32 * k;
            if (i < STATE * NA) sp[i] = __ldg(&acr[i]);
        }
        __syncwarp();

        const float* __restrict__ dem = obs + row * (3 * STATE) + 2 * STATE;
        float* __restrict__ nout = out + 3LL * B + row * STATE;
        float* __restrict__ nrow = s_nsc + wid * STATE;

        float imm = 0.0f;
        #pragma unroll
        for (int k = 0; k < 3; k++) {
            const int c = lane + 32 * k;
            if (c < STATE) {
                const int r   = c / SIDE;
                const int col = c - r * SIDE;
                float v = sp[c * NA + 0];
                if (r == 0)        v += sp[c * NA + 1];
                if (r < SIDE - 1)  v += sp[(c + SIDE) * NA + 1];
                if (r == SIDE - 1) v += sp[c * NA + 2];
                if (r > 0)         v += sp[(c - SIDE) * NA + 2];
                if (col == 0)      v += sp[c * NA + 3];
                if (col < SIDE - 1)v += sp[(c + 1) * NA + 3];
                if (col == SIDE-1) v += sp[c * NA + 4];
                if (col > 0)       v += sp[(c - 1) * NA + 4];

                nout[c] = v;                      // gmem, coalesced
                nrow[c] = v;                      // smem
                imm += fminf(v, __ldg(&dem[c]));
            }
        }

        #pragma unroll
        for (int o = 16; o; o >>= 1) imm += __shfl_xor_sync(0xffffffffu, imm, o);
        if (lane == 0) out[(long long)B + row] = imm;
    }
    __syncthreads();

    // Transposed write: g_nscT[d*B + row0 + j] = s_nsc[j*81 + d]
    for (int i = tid; i < STATE * WARPS_K1; i += 32 * WARPS_K1) {
        const int d = i >> 3;
        const int j = i & 7;
        if (row0 + j < B)
            g_nscT[(long long)d * B + row0 + j] = s_nsc[j * STATE + d];
    }
}

// ---------------------------------------------------------------------------
// Packed f32x2 helpers (sm_103a FFMA2)
// ---------------------------------------------------------------------------
__device__ __forceinline__ unsigned long long pack2(float x) {
    unsigned long long r;
    asm("mov.b64 %0, {%1, %1};" : "=l"(r) : "f"(x));
    return r;
}
__device__ __forceinline__ void ffma2(unsigned long long& d,
                                      unsigned long long a,
                                      unsigned long long b) {
    asm("fma.rn.f32x2 %0, %1, %2, %0;" : "+l"(d) : "l"(a), "l"(b));
}
__device__ __forceinline__ void unpack2(unsigned long long p, float& lo, float& hi) {
    asm("mov.b64 {%0, %1}, %2;" : "=f"(lo), "=f"(hi) : "l"(p));
}

// ---------------------------------------------------------------------------
// K2: thread-per-row, 16 columns per pass (2 passes per layer). Only 16 u64
// accumulator regs live at a time -> ~76-85 regs -> 3 blocks/SM (24 warps).
// nsc streamed coalesced from transposed scratch; pass 2 re-reads hit L1/L2.
// Weight LDS are warp-uniform broadcasts (1 wavefront each).
// ---------------------------------------------------------------------------
__global__ __launch_bounds__(256, 3) void k2_mlp(
    const float* __restrict__ W1,
    const float* __restrict__ W2,
    const float* __restrict__ W3,
    const float* __restrict__ b3,
    float* __restrict__ out,
    int B)
{
    __shared__ float sW1[STATE * H];   // 10.4 KB
    __shared__ float sW2[H * H];       //  4.0 KB
    __shared__ float sW3[H];
    __shared__ float sb3;

    for (int i = threadIdx.x; i < STATE * H; i += 256) sW1[i] = W1[i];
    for (int i = threadIdx.x; i < H * H; i += 256)     sW2[i] = W2[i];
    if (threadIdx.x < H)  sW3[threadIdx.x] = W3[threadIdx.x];
    if (threadIdx.x == 0) sb3 = b3[0];
    __syncthreads();

    const long long b = (long long)blockIdx.x * 256 + threadIdx.x;
    const bool valid = (b < B);
    const long long bc = valid ? b : (long long)(B - 1);   // clamp loads

    float h1[H];   // 32 regs, produced in two half-passes

    // ---- Layer 1: two passes of 16 columns ----
    #pragma unroll
    for (int half = 0; half < 2; half++) {
        const int c0 = 16 * half;
        unsigned long long a0=0, a1=0, a2=0, a3=0, a4=0, a5=0, a6=0, a7=0;
        #pragma unroll 9
        for (int d = 0; d < STATE; d++) {
            const unsigned long long v =
                pack2(__ldg(&g_nscT[(long long)d * B + bc]));
            const ulonglong2* __restrict__ wp =
                reinterpret_cast<const ulonglong2*>(&sW1[d * H + c0]);
            const ulonglong2 wA = wp[0], wB = wp[1], wC = wp[2], wD = wp[3];
            ffma2(a0, v, wA.x); ffma2(a1, v, wA.y);
            ffma2(a2, v, wB.x); ffma2(a3, v, wB.y);
            ffma2(a4, v, wC.x); ffma2(a5, v, wC.y);
            ffma2(a6, v, wD.x); ffma2(a7, v, wD.y);
        }
        float lo, hi;
        unpack2(a0, lo, hi); h1[c0+0] = fmaxf(lo,0.f); h1[c0+1] = fmaxf(hi,0.f);
        unpack2(a1, lo, hi); h1[c0+2] = fmaxf(lo,0.f); h1[c0+3] = fmaxf(hi,0.f);
        unpack2(a2, lo, hi); h1[c0+4] = fmaxf(lo,0.f); h1[c0+5] = fmaxf(hi,0.f);
        unpack2(a3, lo, hi); h1[c0+6] = fmaxf(lo,0.f); h1[c0+7] = fmaxf(hi,0.f);
        unpack2(a4, lo, hi); h1[c0+8] = fmaxf(lo,0.f); h1[c0+9] = fmaxf(hi,0.f);
        unpack2(a5, lo, hi); h1[c0+10]= fmaxf(lo,0.f); h1[c0+11]= fmaxf(hi,0.f);
        unpack2(a6, lo, hi); h1[c0+12]= fmaxf(lo,0.f); h1[c0+13]= fmaxf(hi,0.f);
        unpack2(a7, lo, hi); h1[c0+14]= fmaxf(lo,0.f); h1[c0+15]= fmaxf(hi,0.f);
    }

    // ---- Layer 2 + head: two passes of 16 columns, reduced immediately ----
    float part = 0.0f;
    #pragma unroll
    for (int half = 0; half < 2; half++) {
        const int c0 = 16 * half;
        unsigned long long z0=0, z1=0, z2=0, z3=0, z4=0, z5=0, z6=0, z7=0;
        #pragma unroll
        for (int i = 0; i < H; i++) {
            const unsigned long long v = pack2(h1[i]);
            const ulonglong2* __restrict__ wp =
                reinterpret_cast<const ulonglong2*>(&sW2[i * H + c0]);
            const ulonglong2 wA = wp[0], wB = wp[1], wC = wp[2], wD = wp[3];
            ffma2(z0, v, wA.x); ffma2(z1, v, wA.y);
            ffma2(z2, v, wB.x); ffma2(z3, v, wB.y);
            ffma2(z4, v, wC.x); ffma2(z5, v, wC.y);
            ffma2(z6, v, wD.x); ffma2(z7, v, wD.y);
        }
        const float* __restrict__ w3 = &sW3[c0];
        float lo, hi;
        unpack2(z0, lo, hi); part += fmaxf(lo,0.f)*w3[0]  + fmaxf(hi,0.f)*w3[1];
        unpack2(z1, lo, hi); part += fmaxf(lo,0.f)*w3[2]  + fmaxf(hi,0.f)*w3[3];
        unpack2(z2, lo, hi); part += fmaxf(lo,0.f)*w3[4]  + fmaxf(hi,0.f)*w3[5];
        unpack2(z3, lo, hi); part += fmaxf(lo,0.f)*w3[6]  + fmaxf(hi,0.f)*w3[7];
        unpack2(z4, lo, hi); part += fmaxf(lo,0.f)*w3[8]  + fmaxf(hi,0.f)*w3[9];
        unpack2(z5, lo, hi); part += fmaxf(lo,0.f)*w3[10] + fmaxf(hi,0.f)*w3[11];
        unpack2(z6, lo, hi); part += fmaxf(lo,0.f)*w3[12] + fmaxf(hi,0.f)*w3[13];
        unpack2(z7, lo, hi); part += fmaxf(lo,0.f)*w3[14] + fmaxf(hi,0.f)*w3[15];
    }

    if (valid) {
        const float ret = part + sb3;
        const float imm = __ldg(&out[(long long)B + b]);
        out[b]                      = imm + ret;  // symbolic_val
        out[2LL * (long long)B + b] = ret;        // next_return
    }
}

extern "C" void kernel_launch(void* const* d_in, const int* in_sizes, int n_in,
                              void* d_out, int out_size) {
    const float* obs = (const float*)d_in[0];
    const float* action_count = (const float*)d_in[1];
    const float* W1 = (const float*)d_in[2];
    const float* W2 = (const float*)d_in[3];
    const float* W3 = (const float*)d_in[4];
    const float* b3 = (const float*)d_in[5];
    float* out = (float*)d_out;

    const int B = in_sizes[0] / (3 * STATE);

    const int blocks1 = (B + WARPS_K1 - 1) / WARPS_K1;
    k1_nsc_reward<<<blocks1, 32 * WARPS_K1>>>(obs, action_count, out, B);

    const int blocks2 = (B + 255) / 256;
    k2_mlp<<<blocks2, 256>>>(W1, W2, W3, b3, out, B);
}